// round 10
// baseline (speedup 1.0000x reference)
#include <cuda_runtime.h>
#include <math.h>
#include <stdint.h>

// Problem constants
#define Bn   2
#define Tn   2048
#define En   1024
#define HQn  16
#define HKVn 4
#define Dn   64
#define Gn   4
#define MR   (Bn*Tn)            // 4096 rows
#define KVW  (HKVn*Dn)          // 256
#define YELEMS   (MR*En)                         // 4,194,304
#define ATTELEMS (134217728LL)                   // B*G*HKV*T*T

// Scratch (static device globals: allocation-free at run time)
__device__ float g_q[MR*En];
__device__ float g_k[MR*KVW];
__device__ float g_v[MR*KVW];
__device__ float g_y[MR*En];
__device__ float g_att[134217728];
// RoPE trig tables: [t][i], t in [0,2048), i in [0,32)
__device__ float g_cos[Tn*32];
__device__ float g_sin[Tn*32];

#define NEG_INF __int_as_float(0xff800000)

// ---------------------------------------------------------------------------
// tf32 helpers: split fp32 into hi(tf32) + lo(tf32) for 3xTF32 GEMM.
// ---------------------------------------------------------------------------
__device__ __forceinline__ void split_tf32(float x, uint32_t& hi, uint32_t& lo) {
    asm("cvt.rna.tf32.f32 %0, %1;" : "=r"(hi) : "f"(x));
    float l = x - __uint_as_float(hi);
    asm("cvt.rna.tf32.f32 %0, %1;" : "=r"(lo) : "f"(l));
}

__device__ __forceinline__ void mma_tf32(float c[4], const uint32_t a[4], const uint32_t b[2]) {
    asm volatile(
        "mma.sync.aligned.m16n8k8.row.col.f32.tf32.tf32.f32 "
        "{%0,%1,%2,%3}, {%4,%5,%6,%7}, {%8,%9}, {%0,%1,%2,%3};\n"
        : "+f"(c[0]), "+f"(c[1]), "+f"(c[2]), "+f"(c[3])
        : "r"(a[0]), "r"(a[1]), "r"(a[2]), "r"(a[3]), "r"(b[0]), "r"(b[1]));
}

// ---------------------------------------------------------------------------
// Fill RoPE trig tables. angle = fp32((t+1) * fp32(10000^(-2i/64))), trig in
// double (immune to --use_fast_math at angles up to ~2048 rad).
// ---------------------------------------------------------------------------
__global__ void fill_trig_kernel() {
    int idx = blockIdx.x * blockDim.x + threadIdx.x;
    if (idx >= Tn * 32) return;
    int i = idx & 31;
    int t = idx >> 5;
    float theta = (float)pow(10000.0, -(2.0 * (double)i) / 64.0);
    float ang = __fmul_rn((float)(t + 1), theta);
    double cd, sd;
    sincos((double)ang, &sd, &cd);
    g_cos[idx] = (float)cd;
    g_sin[idx] = (float)sd;
}

// ---------------------------------------------------------------------------
// 3xTF32 tensor-core GEMM + bias: C[M,N] = A[M,K] @ B[K,N] + bias[N]
// 128x128 block tile, BK=16, 256 threads = 8 warps (4M x 2N), warp tile
// 32x64 = 2x8 m16n8k8 fragments. fp32-equivalent accuracy via hi/lo split.
// Requires M%128==0, N%128==0, K%16==0.
// ---------------------------------------------------------------------------
__global__ void gemm3t_bias(const float* __restrict__ A, const float* __restrict__ B,
                            const float* __restrict__ bias, float* __restrict__ C,
                            int M, int N, int K) {
    __shared__ float As[16][132];   // [kk][m] transposed, padded
    __shared__ float Bs[16][132];   // [kk][n], padded
    const int tid  = threadIdx.x;
    const int lane = tid & 31;
    const int warp = tid >> 5;
    const int gid  = lane >> 2;     // group id 0..7
    const int tig  = lane & 3;      // thread-in-group 0..3
    const int wm   = warp >> 1;     // 0..3 (M dim)
    const int wn   = warp & 1;      // 0..1 (N dim)
    const int bm = blockIdx.y * 128;
    const int bn = blockIdx.x * 128;

    float c[2][8][4];
#pragma unroll
    for (int mt = 0; mt < 2; mt++)
#pragma unroll
        for (int nt = 0; nt < 8; nt++)
#pragma unroll
            for (int r = 0; r < 4; r++) c[mt][nt][r] = 0.f;

    for (int k0 = 0; k0 < K; k0 += 16) {
        // A tile 128x16 -> As[kk][m] (transposed store)
#pragma unroll
        for (int l = 0; l < 2; l++) {
            int j = tid + l * 256;
            int row = j >> 2, c4 = (j & 3) * 4;
            float4 v = *(const float4*)&A[(size_t)(bm + row) * K + k0 + c4];
            As[c4 + 0][row] = v.x;
            As[c4 + 1][row] = v.y;
            As[c4 + 2][row] = v.z;
            As[c4 + 3][row] = v.w;
        }
        // B tile 16x128 -> Bs[kk][n]
#pragma unroll
        for (int l = 0; l < 2; l++) {
            int j = tid + l * 256;
            int row = j >> 5, c4 = (j & 31) * 4;
            *(float4*)&Bs[row][c4] = *(const float4*)&B[(size_t)(k0 + row) * N + bn + c4];
        }
        __syncthreads();

#pragma unroll
        for (int ks = 0; ks < 2; ks++) {
            const int kb = ks * 8;
            // A fragments (m16n8k8 row-major): a0[r=gid,c=tig] a1[r=gid+8,c=tig]
            //                                  a2[r=gid,c=tig+4] a3[r=gid+8,c=tig+4]
            uint32_t ahi[2][4], alo[2][4];
#pragma unroll
            for (int mt = 0; mt < 2; mt++) {
                int rb = wm * 32 + mt * 16;
                split_tf32(As[kb + tig][rb + gid],         ahi[mt][0], alo[mt][0]);
                split_tf32(As[kb + tig][rb + gid + 8],     ahi[mt][1], alo[mt][1]);
                split_tf32(As[kb + tig + 4][rb + gid],     ahi[mt][2], alo[mt][2]);
                split_tf32(As[kb + tig + 4][rb + gid + 8], ahi[mt][3], alo[mt][3]);
            }
            // B fragments (col-major view of Bs[k][n]): b0[k=tig,n=gid] b1[k=tig+4,n=gid]
            uint32_t bhi[8][2], blo[8][2];
#pragma unroll
            for (int nt = 0; nt < 8; nt++) {
                int cb = wn * 64 + nt * 8;
                split_tf32(Bs[kb + tig][cb + gid],     bhi[nt][0], blo[nt][0]);
                split_tf32(Bs[kb + tig + 4][cb + gid], bhi[nt][1], blo[nt][1]);
            }
            // 3xTF32: hi*hi + hi*lo + lo*hi
#pragma unroll
            for (int mt = 0; mt < 2; mt++)
#pragma unroll
                for (int nt = 0; nt < 8; nt++) {
                    mma_tf32(c[mt][nt], ahi[mt], bhi[nt]);
                    mma_tf32(c[mt][nt], ahi[mt], blo[nt]);
                    mma_tf32(c[mt][nt], alo[mt], bhi[nt]);
                }
        }
        __syncthreads();
    }

    // Epilogue: bias + store. c0,c1 @ row=gid, cols=2*tig,2*tig+1; c2,c3 @ row=gid+8.
#pragma unroll
    for (int mt = 0; mt < 2; mt++) {
        int r0 = bm + wm * 32 + mt * 16 + gid;
#pragma unroll
        for (int nt = 0; nt < 8; nt++) {
            int col = bn + wn * 64 + nt * 8 + tig * 2;
            float2 bb = *(const float2*)&bias[col];
            float2 v;
            v.x = c[mt][nt][0] + bb.x;
            v.y = c[mt][nt][1] + bb.y;
            *(float2*)&C[(size_t)r0 * N + col] = v;
            v.x = c[mt][nt][2] + bb.x;
            v.y = c[mt][nt][3] + bb.y;
            *(float2*)&C[(size_t)(r0 + 8) * N + col] = v;
        }
    }
}

// ---------------------------------------------------------------------------
// RoPE in place using precomputed trig tables.
// ---------------------------------------------------------------------------
__global__ void rope_kernel(float* __restrict__ x, int nheads) {
    int idx = blockIdx.x * blockDim.x + threadIdx.x;
    int total = MR * nheads * 32;
    if (idx >= total) return;
    int i = idx & 31;
    int h = (idx >> 5) % nheads;
    int r = idx / (32 * nheads);
    int t = r & (Tn - 1);
    float c = g_cos[(t << 5) + i];
    float s = g_sin[(t << 5) + i];
    float* p = x + (size_t)r * (nheads * 64) + h * 64;
    float x1 = p[i], x2 = p[i + 32];
    p[i]      = x1 * c - x2 * s;
    p[i + 32] = x2 * c + x1 * s;
}

// ---------------------------------------------------------------------------
// Causal attention logits: S[q,k] = (Q·K)/8, masked to -inf for k>q.
// ---------------------------------------------------------------------------
__global__ void scores_kernel(const float* __restrict__ q, const float* __restrict__ k,
                              float* __restrict__ att) {
    const int qt = blockIdx.y, kt = blockIdx.z;
    if (kt > qt) return;
    const int head = blockIdx.x;
    const int b = head >> 4, hq = head & 15;
    const int hkv = hq >> 2, g = hq & 3;

    __shared__ float Qs[64][65];
    __shared__ float Ks[64][65];

    const float* qbase = q + ((size_t)b * Tn + qt * 64) * En + hq * 64;
    const float* kbase = k + ((size_t)b * Tn + kt * 64) * KVW + hkv * 64;

#pragma unroll
    for (int i = threadIdx.x; i < 64*64; i += 256) {
        int m = i >> 6, d = i & 63;
        Qs[m][d] = qbase[(size_t)m * En + d];
        Ks[m][d] = kbase[(size_t)m * KVW + d];
    }
    __syncthreads();

    const int tx = threadIdx.x & 15, ty = threadIdx.x >> 4;
    float acc[4][4];
#pragma unroll
    for (int i = 0; i < 4; i++)
#pragma unroll
        for (int j = 0; j < 4; j++) acc[i][j] = 0.f;

#pragma unroll 16
    for (int d = 0; d < 64; d++) {
        float a[4], bb[4];
#pragma unroll
        for (int i = 0; i < 4; i++) a[i] = Qs[ty*4 + i][d];
#pragma unroll
        for (int j = 0; j < 4; j++) bb[j] = Ks[tx*4 + j][d];
#pragma unroll
        for (int i = 0; i < 4; i++)
#pragma unroll
            for (int j = 0; j < 4; j++) acc[i][j] = fmaf(a[i], bb[j], acc[i][j]);
    }

    float* obase = att + ((size_t)(b*16 + g*4 + hkv) * Tn + qt * 64) * Tn + kt * 64;
#pragma unroll
    for (int i = 0; i < 4; i++) {
        int qg = qt*64 + ty*4 + i;
#pragma unroll
        for (int j = 0; j < 4; j++) {
            int kg = kt*64 + tx*4 + j;
            float v = (kg > qg) ? NEG_INF : acc[i][j] * 0.125f;
            obase[(size_t)(ty*4 + i) * Tn + (tx*4 + j)] = v;
        }
    }
}

// ---------------------------------------------------------------------------
// Row softmax, in place. Valid length = q+1; masked tail written as exact 0.
// ---------------------------------------------------------------------------
__global__ void softmax_kernel(float* __restrict__ att) {
    const int rid = blockIdx.x;
    const int qpos = rid & (Tn - 1);
    const int L = qpos + 1;
    float* row = att + (size_t)rid * Tn;

    __shared__ float buf[Tn];
    __shared__ float red[256];
    const int tid = threadIdx.x;

    float m = NEG_INF;
    for (int k = tid; k < L; k += 256) {
        float v = row[k];
        buf[k] = v;
        m = fmaxf(m, v);
    }
    red[tid] = m; __syncthreads();
    for (int s = 128; s > 0; s >>= 1) {
        if (tid < s) red[tid] = fmaxf(red[tid], red[tid + s]);
        __syncthreads();
    }
    m = red[0]; __syncthreads();

    float sum = 0.f;
    for (int k = tid; k < L; k += 256) {
        float e = expf(buf[k] - m);
        buf[k] = e;
        sum += e;
    }
    red[tid] = sum; __syncthreads();
    for (int s = 128; s > 0; s >>= 1) {
        if (tid < s) red[tid] += red[tid + s];
        __syncthreads();
    }
    const float inv = 1.f / red[0];

    for (int k = tid; k < Tn; k += 256) {
        row[k] = (k < L) ? buf[k] * inv : 0.f;
    }
}

// ---------------------------------------------------------------------------
// y = att @ V per head. grid: (32 heads, 32 qtiles). Only causal k-range.
// ---------------------------------------------------------------------------
__global__ void av_kernel(const float* __restrict__ att, const float* __restrict__ v,
                          float* __restrict__ y) {
    const int head = blockIdx.x, qt = blockIdx.y;
    const int b = head >> 4, hq = head & 15;
    const int hkv = hq >> 2, g = hq & 3;

    __shared__ float As[64][33];
    __shared__ float Vs[32][64];

    const float* abase = att + ((size_t)(b*16 + g*4 + hkv) * Tn + qt * 64) * Tn;
    const float* vbase = v + (size_t)b * Tn * KVW + hkv * 64;

    const int tx = threadIdx.x & 15, ty = threadIdx.x >> 4;
    float acc[4][4];
#pragma unroll
    for (int i = 0; i < 4; i++)
#pragma unroll
        for (int j = 0; j < 4; j++) acc[i][j] = 0.f;

    const int kend = (qt + 1) * 64;
    for (int k0 = 0; k0 < kend; k0 += 32) {
#pragma unroll
        for (int i = threadIdx.x; i < 64*32; i += 256) {
            int m = i >> 5, kk = i & 31;
            As[m][kk] = abase[(size_t)m * Tn + k0 + kk];
        }
#pragma unroll
        for (int i = threadIdx.x; i < 32*64; i += 256) {
            int kk = i >> 6, n = i & 63;
            Vs[kk][n] = vbase[(size_t)(k0 + kk) * KVW + n];
        }
        __syncthreads();
#pragma unroll
        for (int kk = 0; kk < 32; kk++) {
            float a[4], bb[4];
#pragma unroll
            for (int i = 0; i < 4; i++) a[i] = As[ty*4 + i][kk];
#pragma unroll
            for (int j = 0; j < 4; j++) bb[j] = Vs[kk][tx*4 + j];
#pragma unroll
            for (int i = 0; i < 4; i++)
#pragma unroll
                for (int j = 0; j < 4; j++) acc[i][j] = fmaf(a[i], bb[j], acc[i][j]);
        }
        __syncthreads();
    }
#pragma unroll
    for (int i = 0; i < 4; i++) {
        int row = b * Tn + qt*64 + ty*4 + i;
#pragma unroll
        for (int j = 0; j < 4; j++) {
            y[(size_t)row * En + hq*64 + tx*4 + j] = acc[i][j];
        }
    }
}

// ---------------------------------------------------------------------------
extern "C" void kernel_launch(void* const* d_in, const int* in_sizes, int n_in,
                              void* d_out, int out_size) {
    const float* x  = (const float*)d_in[0];
    // d_in[1] = mask (int32) — static causal, unused
    const float* Wq = (const float*)d_in[2];
    const float* bq = (const float*)d_in[3];
    const float* Wk = (const float*)d_in[4];
    const float* bk = (const float*)d_in[5];
    const float* Wv = (const float*)d_in[6];
    const float* bv = (const float*)d_in[7];
    const float* Wo = (const float*)d_in[8];
    const float* bo = (const float*)d_in[9];

    float *pq, *pk, *pv, *py, *patt;
    cudaGetSymbolAddress((void**)&pq, g_q);
    cudaGetSymbolAddress((void**)&pk, g_k);
    cudaGetSymbolAddress((void**)&pv, g_v);
    cudaGetSymbolAddress((void**)&py, g_y);
    cudaGetSymbolAddress((void**)&patt, g_att);

    float* out = (float*)d_out;
    float* y_out = nullptr;
    float* att;
    long long osz = (long long)out_size;
    if (osz >= (long long)YELEMS + ATTELEMS) {
        y_out = out;
        att = out + YELEMS;
    } else if (osz == ATTELEMS) {
        att = out;                 // att-only output
    } else {
        y_out = out;               // y-only output; att is scratch
        att = patt;
    }

    // 0) RoPE trig tables
    fill_trig_kernel<<<(Tn*32 + 255)/256, 256>>>();

    // 1) Projections (3xTF32 tensor-core GEMM)
    gemm3t_bias<<<dim3(En/128,  MR/128), 256>>>(x, Wq, bq, pq, MR, En,  En);
    gemm3t_bias<<<dim3(KVW/128, MR/128), 256>>>(x, Wk, bk, pk, MR, KVW, En);
    gemm3t_bias<<<dim3(KVW/128, MR/128), 256>>>(x, Wv, bv, pv, MR, KVW, En);

    // 2) RoPE on q and k (table-driven)
    rope_kernel<<<(MR*HQn*32  + 255)/256, 256>>>(pq, HQn);
    rope_kernel<<<(MR*HKVn*32 + 255)/256, 256>>>(pk, HKVn);

    // 3) Causal logits
    scores_kernel<<<dim3(Bn*HQn, Tn/64, Tn/64), 256>>>(pq, pk, att);

    // 4) Row softmax in place (also zero-fills masked tail)
    softmax_kernel<<<Bn*HQn*Tn, 256>>>(att);

    // 5) y = att @ V
    av_kernel<<<dim3(Bn*HQn, Tn/64), 256>>>(att, pv, py);

    // 6) Output projection (3xTF32)
    if (y_out) {
        gemm3t_bias<<<dim3(En/128, MR/128), 256>>>(py, Wo, bo, y_out, MR, En, En);
    }
}

// round 11
// speedup vs baseline: 1.1276x; 1.1276x over previous
#include <cuda_runtime.h>
#include <math.h>
#include <stdint.h>

// Problem constants
#define Bn   2
#define Tn   2048
#define En   1024
#define HQn  16
#define HKVn 4
#define Dn   64
#define Gn   4
#define MR   (Bn*Tn)            // 4096 rows
#define KVW  (HKVn*Dn)          // 256
#define YELEMS   (MR*En)                         // 4,194,304
#define ATTELEMS (134217728LL)                   // B*G*HKV*T*T

// Scratch (static device globals: allocation-free at run time)
__device__ float g_q[MR*En];
__device__ float g_k[MR*KVW];
__device__ float g_v[MR*KVW];
__device__ float g_y[MR*En];
__device__ float g_att[134217728];
// RoPE trig tables: [t][i], t in [0,2048), i in [0,32)
__device__ float g_cos[Tn*32];
__device__ float g_sin[Tn*32];

#define NEG_INF __int_as_float(0xff800000)

// ---------------------------------------------------------------------------
// tf32 helpers
// ---------------------------------------------------------------------------
__device__ __forceinline__ void split_tf32(float x, float& hi, float& lo) {
    uint32_t h;
    asm("cvt.rna.tf32.f32 %0, %1;" : "=r"(h) : "f"(x));
    hi = __uint_as_float(h);
    float l = x - hi;
    uint32_t lo32;
    asm("cvt.rna.tf32.f32 %0, %1;" : "=r"(lo32) : "f"(l));
    lo = __uint_as_float(lo32);
}

__device__ __forceinline__ void mma_tf32(float c[4], const uint32_t a[4], const uint32_t b[2]) {
    asm volatile(
        "mma.sync.aligned.m16n8k8.row.col.f32.tf32.tf32.f32 "
        "{%0,%1,%2,%3}, {%4,%5,%6,%7}, {%8,%9}, {%0,%1,%2,%3};\n"
        : "+f"(c[0]), "+f"(c[1]), "+f"(c[2]), "+f"(c[3])
        : "r"(a[0]), "r"(a[1]), "r"(a[2]), "r"(a[3]), "r"(b[0]), "r"(b[1]));
}

// ---------------------------------------------------------------------------
// Fill RoPE trig tables.
// ---------------------------------------------------------------------------
__global__ void fill_trig_kernel() {
    int idx = blockIdx.x * blockDim.x + threadIdx.x;
    if (idx >= Tn * 32) return;
    int i = idx & 31;
    int t = idx >> 5;
    float theta = (float)pow(10000.0, -(2.0 * (double)i) / 64.0);
    float ang = __fmul_rn((float)(t + 1), theta);
    double cd, sd;
    sincos((double)ang, &sd, &cd);
    g_cos[idx] = (float)cd;
    g_sin[idx] = (float)sd;
}

// ---------------------------------------------------------------------------
// 3xTF32 tensor-core GEMM tile body: C[bm:bm+128, bn:bn+128] = A@B + bias.
// hi/lo split done ONCE at smem-load time; inner loop is pure LDS + HMMA.
// 256 threads = 8 warps (4M x 2N), warp tile 32x64 = 2x8 m16n8k8 frags.
// ---------------------------------------------------------------------------
__device__ __forceinline__ void gemm3t_tile(
    const float* __restrict__ A, const float* __restrict__ B,
    const float* __restrict__ bias, float* __restrict__ C,
    int N, int K, int bm, int bn)
{
    __shared__ float Ahi[16][132], Alo[16][132];   // [kk][m] transposed
    __shared__ float Bhi[16][132], Blo[16][132];   // [kk][n]
    const int tid  = threadIdx.x;
    const int lane = tid & 31;
    const int warp = tid >> 5;
    const int gid  = lane >> 2;
    const int tig  = lane & 3;
    const int wm   = warp >> 1;
    const int wn   = warp & 1;

    float c[2][8][4];
#pragma unroll
    for (int mt = 0; mt < 2; mt++)
#pragma unroll
        for (int nt = 0; nt < 8; nt++)
#pragma unroll
            for (int r = 0; r < 4; r++) c[mt][nt][r] = 0.f;

    for (int k0 = 0; k0 < K; k0 += 16) {
        // A tile 128x16 -> Ahi/Alo[kk][m] (transposed store, split at load)
#pragma unroll
        for (int l = 0; l < 2; l++) {
            int j = tid + l * 256;
            int row = j >> 2, c4 = (j & 3) * 4;
            float4 v = *(const float4*)&A[(size_t)(bm + row) * K + k0 + c4];
            float h, lo;
            split_tf32(v.x, h, lo); Ahi[c4 + 0][row] = h; Alo[c4 + 0][row] = lo;
            split_tf32(v.y, h, lo); Ahi[c4 + 1][row] = h; Alo[c4 + 1][row] = lo;
            split_tf32(v.z, h, lo); Ahi[c4 + 2][row] = h; Alo[c4 + 2][row] = lo;
            split_tf32(v.w, h, lo); Ahi[c4 + 3][row] = h; Alo[c4 + 3][row] = lo;
        }
        // B tile 16x128 -> Bhi/Blo[kk][n]
#pragma unroll
        for (int l = 0; l < 2; l++) {
            int j = tid + l * 256;
            int row = j >> 5, c4 = (j & 31) * 4;
            float4 v = *(const float4*)&B[(size_t)(k0 + row) * N + bn + c4];
            float h, lo;
            split_tf32(v.x, h, lo); Bhi[row][c4 + 0] = h; Blo[row][c4 + 0] = lo;
            split_tf32(v.y, h, lo); Bhi[row][c4 + 1] = h; Blo[row][c4 + 1] = lo;
            split_tf32(v.z, h, lo); Bhi[row][c4 + 2] = h; Blo[row][c4 + 2] = lo;
            split_tf32(v.w, h, lo); Bhi[row][c4 + 3] = h; Blo[row][c4 + 3] = lo;
        }
        __syncthreads();

#pragma unroll
        for (int ks = 0; ks < 2; ks++) {
            const int kb = ks * 8;
            uint32_t ahi[2][4], alo[2][4];
#pragma unroll
            for (int mt = 0; mt < 2; mt++) {
                int rb = wm * 32 + mt * 16;
                ahi[mt][0] = __float_as_uint(Ahi[kb + tig][rb + gid]);
                ahi[mt][1] = __float_as_uint(Ahi[kb + tig][rb + gid + 8]);
                ahi[mt][2] = __float_as_uint(Ahi[kb + tig + 4][rb + gid]);
                ahi[mt][3] = __float_as_uint(Ahi[kb + tig + 4][rb + gid + 8]);
                alo[mt][0] = __float_as_uint(Alo[kb + tig][rb + gid]);
                alo[mt][1] = __float_as_uint(Alo[kb + tig][rb + gid + 8]);
                alo[mt][2] = __float_as_uint(Alo[kb + tig + 4][rb + gid]);
                alo[mt][3] = __float_as_uint(Alo[kb + tig + 4][rb + gid + 8]);
            }
#pragma unroll
            for (int nt = 0; nt < 8; nt++) {
                int cb = wn * 64 + nt * 8;
                uint32_t bh[2], bl[2];
                bh[0] = __float_as_uint(Bhi[kb + tig][cb + gid]);
                bh[1] = __float_as_uint(Bhi[kb + tig + 4][cb + gid]);
                bl[0] = __float_as_uint(Blo[kb + tig][cb + gid]);
                bl[1] = __float_as_uint(Blo[kb + tig + 4][cb + gid]);
#pragma unroll
                for (int mt = 0; mt < 2; mt++) {
                    mma_tf32(c[mt][nt], ahi[mt], bh);
                    mma_tf32(c[mt][nt], ahi[mt], bl);
                    mma_tf32(c[mt][nt], alo[mt], bh);
                }
            }
        }
        __syncthreads();
    }

    // Epilogue: bias + store.
#pragma unroll
    for (int mt = 0; mt < 2; mt++) {
        int r0 = bm + wm * 32 + mt * 16 + gid;
#pragma unroll
        for (int nt = 0; nt < 8; nt++) {
            int col = bn + wn * 64 + nt * 8 + tig * 2;
            float2 bb = *(const float2*)&bias[col];
            float2 v;
            v.x = c[mt][nt][0] + bb.x;
            v.y = c[mt][nt][1] + bb.y;
            *(float2*)&C[(size_t)r0 * N + col] = v;
            v.x = c[mt][nt][2] + bb.x;
            v.y = c[mt][nt][3] + bb.y;
            *(float2*)&C[(size_t)(r0 + 8) * N + col] = v;
        }
    }
}

// Generic single-GEMM wrapper (used for Wo).
__global__ __launch_bounds__(256, 2)
void gemm3t_bias(const float* __restrict__ A, const float* __restrict__ B,
                 const float* __restrict__ bias, float* __restrict__ C,
                 int M, int N, int K) {
    gemm3t_tile(A, B, bias, C, N, K, blockIdx.y * 128, blockIdx.x * 128);
}

// Fused Q/K/V projection: grid.x = 12 column-tiles (8 Q, 2 K, 2 V).
__global__ __launch_bounds__(256, 2)
void gemm3t_qkv(const float* __restrict__ x,
                const float* __restrict__ Wq, const float* __restrict__ bq, float* __restrict__ q,
                const float* __restrict__ Wk, const float* __restrict__ bk, float* __restrict__ k,
                const float* __restrict__ Wv, const float* __restrict__ bv, float* __restrict__ v) {
    const int ct = blockIdx.x;
    const int bm = blockIdx.y * 128;
    if (ct < 8)       gemm3t_tile(x, Wq, bq, q, En,  En, bm, ct * 128);
    else if (ct < 10) gemm3t_tile(x, Wk, bk, k, KVW, En, bm, (ct - 8) * 128);
    else              gemm3t_tile(x, Wv, bv, v, KVW, En, bm, (ct - 10) * 128);
}

// ---------------------------------------------------------------------------
// RoPE in place using precomputed trig tables.
// ---------------------------------------------------------------------------
__global__ void rope_kernel(float* __restrict__ x, int nheads) {
    int idx = blockIdx.x * blockDim.x + threadIdx.x;
    int total = MR * nheads * 32;
    if (idx >= total) return;
    int i = idx & 31;
    int h = (idx >> 5) % nheads;
    int r = idx / (32 * nheads);
    int t = r & (Tn - 1);
    float c = g_cos[(t << 5) + i];
    float s = g_sin[(t << 5) + i];
    float* p = x + (size_t)r * (nheads * 64) + h * 64;
    float x1 = p[i], x2 = p[i + 32];
    p[i]      = x1 * c - x2 * s;
    p[i + 32] = x2 * c + x1 * s;
}

// ---------------------------------------------------------------------------
// Causal attention logits: S[q,k] = (Q·K)/8, masked to -inf for k>q.
// ---------------------------------------------------------------------------
__global__ void scores_kernel(const float* __restrict__ q, const float* __restrict__ k,
                              float* __restrict__ att) {
    const int qt = blockIdx.y, kt = blockIdx.z;
    if (kt > qt) return;
    const int head = blockIdx.x;
    const int b = head >> 4, hq = head & 15;
    const int hkv = hq >> 2, g = hq & 3;

    __shared__ float Qs[64][65];
    __shared__ float Ks[64][65];

    const float* qbase = q + ((size_t)b * Tn + qt * 64) * En + hq * 64;
    const float* kbase = k + ((size_t)b * Tn + kt * 64) * KVW + hkv * 64;

#pragma unroll
    for (int i = threadIdx.x; i < 64*64; i += 256) {
        int m = i >> 6, d = i & 63;
        Qs[m][d] = qbase[(size_t)m * En + d];
        Ks[m][d] = kbase[(size_t)m * KVW + d];
    }
    __syncthreads();

    const int tx = threadIdx.x & 15, ty = threadIdx.x >> 4;
    float acc[4][4];
#pragma unroll
    for (int i = 0; i < 4; i++)
#pragma unroll
        for (int j = 0; j < 4; j++) acc[i][j] = 0.f;

#pragma unroll 16
    for (int d = 0; d < 64; d++) {
        float a[4], bb[4];
#pragma unroll
        for (int i = 0; i < 4; i++) a[i] = Qs[ty*4 + i][d];
#pragma unroll
        for (int j = 0; j < 4; j++) bb[j] = Ks[tx*4 + j][d];
#pragma unroll
        for (int i = 0; i < 4; i++)
#pragma unroll
            for (int j = 0; j < 4; j++) acc[i][j] = fmaf(a[i], bb[j], acc[i][j]);
    }

    float* obase = att + ((size_t)(b*16 + g*4 + hkv) * Tn + qt * 64) * Tn + kt * 64;
#pragma unroll
    for (int i = 0; i < 4; i++) {
        int qg = qt*64 + ty*4 + i;
#pragma unroll
        for (int j = 0; j < 4; j++) {
            int kg = kt*64 + tx*4 + j;
            float v = (kg > qg) ? NEG_INF : acc[i][j] * 0.125f;
            obase[(size_t)(ty*4 + i) * Tn + (tx*4 + j)] = v;
        }
    }
}

// ---------------------------------------------------------------------------
// Row softmax, in place. Valid length = q+1; masked tail written as exact 0.
// ---------------------------------------------------------------------------
__global__ void softmax_kernel(float* __restrict__ att) {
    const int rid = blockIdx.x;
    const int qpos = rid & (Tn - 1);
    const int L = qpos + 1;
    float* row = att + (size_t)rid * Tn;

    __shared__ float buf[Tn];
    __shared__ float red[256];
    const int tid = threadIdx.x;

    float m = NEG_INF;
    for (int k = tid; k < L; k += 256) {
        float v = row[k];
        buf[k] = v;
        m = fmaxf(m, v);
    }
    red[tid] = m; __syncthreads();
    for (int s = 128; s > 0; s >>= 1) {
        if (tid < s) red[tid] = fmaxf(red[tid], red[tid + s]);
        __syncthreads();
    }
    m = red[0]; __syncthreads();

    float sum = 0.f;
    for (int k = tid; k < L; k += 256) {
        float e = expf(buf[k] - m);
        buf[k] = e;
        sum += e;
    }
    red[tid] = sum; __syncthreads();
    for (int s = 128; s > 0; s >>= 1) {
        if (tid < s) red[tid] += red[tid + s];
        __syncthreads();
    }
    const float inv = 1.f / red[0];

    for (int k = tid; k < Tn; k += 256) {
        row[k] = (k < L) ? buf[k] * inv : 0.f;
    }
}

// ---------------------------------------------------------------------------
// y = att @ V per head. grid: (32 heads, 32 qtiles). Only causal k-range.
// ---------------------------------------------------------------------------
__global__ void av_kernel(const float* __restrict__ att, const float* __restrict__ v,
                          float* __restrict__ y) {
    const int head = blockIdx.x, qt = blockIdx.y;
    const int b = head >> 4, hq = head & 15;
    const int hkv = hq >> 2, g = hq & 3;

    __shared__ float As[64][33];
    __shared__ float Vs[32][64];

    const float* abase = att + ((size_t)(b*16 + g*4 + hkv) * Tn + qt * 64) * Tn;
    const float* vbase = v + (size_t)b * Tn * KVW + hkv * 64;

    const int tx = threadIdx.x & 15, ty = threadIdx.x >> 4;
    float acc[4][4];
#pragma unroll
    for (int i = 0; i < 4; i++)
#pragma unroll
        for (int j = 0; j < 4; j++) acc[i][j] = 0.f;

    const int kend = (qt + 1) * 64;
    for (int k0 = 0; k0 < kend; k0 += 32) {
#pragma unroll
        for (int i = threadIdx.x; i < 64*32; i += 256) {
            int m = i >> 5, kk = i & 31;
            As[m][kk] = abase[(size_t)m * Tn + k0 + kk];
        }
#pragma unroll
        for (int i = threadIdx.x; i < 32*64; i += 256) {
            int kk = i >> 6, n = i & 63;
            Vs[kk][n] = vbase[(size_t)(k0 + kk) * KVW + n];
        }
        __syncthreads();
#pragma unroll
        for (int kk = 0; kk < 32; kk++) {
            float a[4], bb[4];
#pragma unroll
            for (int i = 0; i < 4; i++) a[i] = As[ty*4 + i][kk];
#pragma unroll
            for (int j = 0; j < 4; j++) bb[j] = Vs[kk][tx*4 + j];
#pragma unroll
            for (int i = 0; i < 4; i++)
#pragma unroll
                for (int j = 0; j < 4; j++) acc[i][j] = fmaf(a[i], bb[j], acc[i][j]);
        }
        __syncthreads();
    }
#pragma unroll
    for (int i = 0; i < 4; i++) {
        int row = b * Tn + qt*64 + ty*4 + i;
#pragma unroll
        for (int j = 0; j < 4; j++) {
            y[(size_t)row * En + hq*64 + tx*4 + j] = acc[i][j];
        }
    }
}

// ---------------------------------------------------------------------------
extern "C" void kernel_launch(void* const* d_in, const int* in_sizes, int n_in,
                              void* d_out, int out_size) {
    const float* x  = (const float*)d_in[0];
    // d_in[1] = mask (int32) — static causal, unused
    const float* Wq = (const float*)d_in[2];
    const float* bq = (const float*)d_in[3];
    const float* Wk = (const float*)d_in[4];
    const float* bk = (const float*)d_in[5];
    const float* Wv = (const float*)d_in[6];
    const float* bv = (const float*)d_in[7];
    const float* Wo = (const float*)d_in[8];
    const float* bo = (const float*)d_in[9];

    float *pq, *pk, *pv, *py, *patt;
    cudaGetSymbolAddress((void**)&pq, g_q);
    cudaGetSymbolAddress((void**)&pk, g_k);
    cudaGetSymbolAddress((void**)&pv, g_v);
    cudaGetSymbolAddress((void**)&py, g_y);
    cudaGetSymbolAddress((void**)&patt, g_att);

    float* out = (float*)d_out;
    float* y_out = nullptr;
    float* att;
    long long osz = (long long)out_size;
    if (osz >= (long long)YELEMS + ATTELEMS) {
        y_out = out;
        att = out + YELEMS;
    } else if (osz == ATTELEMS) {
        att = out;                 // att-only output
    } else {
        y_out = out;               // y-only output; att is scratch
        att = patt;
    }

    // 0) RoPE trig tables
    fill_trig_kernel<<<(Tn*32 + 255)/256, 256>>>();

    // 1) Fused QKV projection (3xTF32 tensor-core, split-in-smem)
    gemm3t_qkv<<<dim3(12, MR/128), 256>>>(x, Wq, bq, pq, Wk, bk, pk, Wv, bv, pv);

    // 2) RoPE on q and k (table-driven)
    rope_kernel<<<(MR*HQn*32  + 255)/256, 256>>>(pq, HQn);
    rope_kernel<<<(MR*HKVn*32 + 255)/256, 256>>>(pk, HKVn);

    // 3) Causal logits
    scores_kernel<<<dim3(Bn*HQn, Tn/64, Tn/64), 256>>>(pq, pk, att);

    // 4) Row softmax in place (also zero-fills masked tail)
    softmax_kernel<<<Bn*HQn*Tn, 256>>>(att);

    // 5) y = att @ V
    av_kernel<<<dim3(Bn*HQn, Tn/64), 256>>>(att, pv, py);

    // 6) Output projection (3xTF32)
    if (y_out) {
        gemm3t_bias<<<dim3(En/128, MR/128), 256>>>(py, Wo, bo, y_out, MR, En, En);
    }
}